// round 15
// baseline (speedup 1.0000x reference)
#include <cuda_runtime.h>
#include <cuda_bf16.h>

typedef unsigned int u32;

// ---------------------------------------------------------------------------
// Problem constants
// ---------------------------------------------------------------------------
namespace {
constexpr int kT = 2048;
constexpr int kS = 512;
constexpr int kB = 16;
constexpr int kA = 18;
constexpr int kColsTot = 336;           // 288 + 32 + 16
constexpr int kRowsPerBlk = 32;         // two 16-row MMA groups
constexpr int kBlkSteps = 16;
constexpr int kNWin = 128;              // 16-step windows
constexpr int kNB2 = 64;                // compose blocks (2 windows each)
constexpr int kGrid = 65;               // 64 + 1 (rows 2048..)
constexpr int kThreads = 672;           // 21 warps
constexpr int kK2 = 256;                // k-pairs (bf16x2 along K)
constexpr int kAStrideU = 260;          // smA row stride (u32)
constexpr int kWStrideU = 36;           // smW col stride (u32)
constexpr int kTileK2 = 32;             // k-pairs per W tile
constexpr int kNIt = 8;
constexpr int kWTileU = kColsTot * kWStrideU;   // 12096
// smem layout (u32 units)
constexpr int kOffA  = 0;                        // 32*260 = 8320
constexpr int kOffW  = 8320;                     // 3 tiles -> 44608
// serial-phase M cache spans [0, 40960)
constexpr int kOffE0 = 44608;                    // 32 steps x 16
constexpr int kOffE1 = kOffE0 + 512;
constexpr int kOffEs = kOffE1 + 512;
constexpr int kOffEa = kOffEs + 512;
constexpr int kOffY  = kOffEa + 512;             // 32 steps x 16
constexpr int kSmemU = kOffY + 512;              // 47168
constexpr int kSmemBytes = kSmemU * 4;           // 188672
constexpr int kMStrideRow = 20;
constexpr int kMStrideMat = 320;
}
#define EXP_NEG_PEN 0.60653065971263342f
#define LN2 0.69314718055994530942

// Cross-kernel / cross-block scratch.
__device__ u32    g_WbT[kColsTot * kK2];   // W transposed, bf16x2 k-paired
__device__ float  g_M[kNWin * 256];
__device__ float  g_chk[(kNWin + 1) * kB];
__device__ int    g_Eb[kNWin + 1];
__device__ float  g_es0_fin[kB];
__device__ double g_tot;
__device__ unsigned g_mcnt;
__device__ unsigned g_rcnt;

struct Bar { unsigned cnt; unsigned gen; };
__device__ Bar g_bars[2];

__device__ __forceinline__ void gbar(int id, unsigned nb) {
    __syncthreads();
    if (threadIdx.x == 0) {
        __threadfence();
        volatile unsigned* vgen = &g_bars[id].gen;
        unsigned g0 = *vgen;
        unsigned prev = atomicAdd(&g_bars[id].cnt, 1u);
        if (prev == nb - 1u) {
            g_bars[id].cnt = 0u;
            __threadfence();
            atomicAdd(&g_bars[id].gen, 1u);
        } else {
            while (*vgen == g0) { __nanosleep(64); }
            __threadfence();
        }
    }
    __syncthreads();
}

// ---------------------------------------------------------------------------
// helpers
// ---------------------------------------------------------------------------
__device__ __forceinline__ void cp_async16(void* sdst, const void* gsrc) {
    unsigned a = (unsigned)__cvta_generic_to_shared(sdst);
    asm volatile("cp.async.cg.shared.global [%0], [%1], 16;" :: "r"(a), "l"(gsrc));
}
#define CP_COMMIT() asm volatile("cp.async.commit_group;")
#define CP_WAIT1()  asm volatile("cp.async.wait_group 1;")
#define CP_WAIT0()  asm volatile("cp.async.wait_group 0;")

__device__ __forceinline__ u32 pack_bf16(float lo, float hi) {
    unsigned short l = __bfloat16_as_ushort(__float2bfloat16_rn(lo));
    unsigned short h = __bfloat16_as_ushort(__float2bfloat16_rn(hi));
    return ((u32)h << 16) | (u32)l;
}
__device__ __forceinline__ void mma_bf16(float c[4], u32 a0, u32 a1, u32 a2,
                                         u32 a3, u32 b0, u32 b1) {
    asm("mma.sync.aligned.m16n8k16.row.col.f32.bf16.bf16.f32 "
        "{%0,%1,%2,%3},{%4,%5,%6,%7},{%8,%9},{%0,%1,%2,%3};"
        : "+f"(c[0]), "+f"(c[1]), "+f"(c[2]), "+f"(c[3])
        : "r"(a0), "r"(a1), "r"(a2), "r"(a3), "r"(b0), "r"(b1));
}
__device__ __forceinline__ void load16s(float d[16], const float* p) {
    const float4* p4 = (const float4*)p;
    float4 a = p4[0], b = p4[1], c = p4[2], e = p4[3];
    d[0]=a.x; d[1]=a.y; d[2]=a.z; d[3]=a.w;
    d[4]=b.x; d[5]=b.y; d[6]=b.z; d[7]=b.w;
    d[8]=c.x; d[9]=c.y; d[10]=c.z; d[11]=c.w;
    d[12]=e.x; d[13]=e.y; d[14]=e.z; d[15]=e.w;
}
__device__ __forceinline__ void load16g(float d[16], const float* p) {
    float4 a = __ldcg((const float4*)p);
    float4 b = __ldcg((const float4*)p + 1);
    float4 c = __ldcg((const float4*)p + 2);
    float4 e = __ldcg((const float4*)p + 3);
    d[0]=a.x; d[1]=a.y; d[2]=a.z; d[3]=a.w;
    d[4]=b.x; d[5]=b.y; d[6]=b.z; d[7]=b.w;
    d[8]=c.x; d[9]=c.y; d[10]=c.z; d[11]=c.w;
    d[12]=e.x; d[13]=e.y; d[14]=e.z; d[15]=e.w;
}
__device__ __forceinline__ float tree16(const float v[16]) {
    float a0=v[0]+v[1], a1=v[2]+v[3], a2=v[4]+v[5], a3=v[6]+v[7];
    float a4=v[8]+v[9], a5=v[10]+v[11], a6=v[12]+v[13], a7=v[14]+v[15];
    float b0=a0+a1, b1=a2+a3, b2=a4+a5, b3=a6+a7;
    return (b0+b1)+(b2+b3);
}

// ---------------------------------------------------------------------------
// K0: convert W -> transposed bf16 pairs
// ---------------------------------------------------------------------------
__global__ __launch_bounds__(256) void convert_w_kernel(
    const float* __restrict__ Wa,
    const float* __restrict__ Wsp,
    const float* __restrict__ Wst) {
    int idx = blockIdx.x * 256 + threadIdx.x;
    if (idx >= kColsTot * kK2) return;
    int k2 = idx / kColsTot;
    int col = idx - k2 * kColsTot;
    const float* base; int stride, off;
    if (col < 288)      { base = Wa;  stride = 288; off = col; }
    else if (col < 320) { base = Wsp; stride = 32;  off = col - 288; }
    else                { base = Wst; stride = 16;  off = col - 320; }
    float x0 = base[(2 * k2    ) * stride + off];
    float x1 = base[(2 * k2 + 1) * stride + off];
    g_WbT[col * kK2 + k2] = pack_bf16(x0, x1);
}

// ---------------------------------------------------------------------------
// K1: fused — A-pack(32 rows), GEMM(M=32), softmax, 2-warp compose(+y),
//     serial scan, y-dot tot
// ---------------------------------------------------------------------------
__global__ __launch_bounds__(kThreads) void fused_kernel(
    const float* __restrict__ s_i,
    const void* __restrict__ actions_raw,
    float* __restrict__ out) {
    extern __shared__ __align__(16) u32 smem[];
    u32* smA = smem + kOffA;
    u32* smW = smem + kOffW;
    float* smL = (float*)(smem + kOffW);     // logits alias W buf0 after GEMM
    float* sE0 = (float*)(smem + kOffE0);
    float* sE1 = (float*)(smem + kOffE1);
    float* sEs = (float*)(smem + kOffEs);
    float* sEa = (float*)(smem + kOffEa);
    float* sY  = (float*)(smem + kOffY);
    __shared__ int s_is64;

    const int tid  = threadIdx.x;
    const int blk  = blockIdx.x;
    const int row0 = blk * kRowsPerBlk;

    if (tid == 0) {
        const unsigned* w = (const unsigned*)actions_raw;
        unsigned acc = 0;
#pragma unroll
        for (int j = 1; j < 64; j += 2) acc |= w[j];
        s_is64 = (acc == 0u) ? 1 : 0;
    }

    // ---- Phase 1a: W prestage (tiles p0, p0+1) + in-register A-pack ----
    const int p0 = blk & (kNIt - 1);
    {
        int tk2 = p0 * kTileK2;
#pragma unroll
        for (int h = 0; h < 4; h++) {
            int q = tid + h * kThreads;
            int col = q >> 3, ch = q & 7;
            cp_async16(smW + col * kWStrideU + ch * 4,
                       g_WbT + col * kK2 + tk2 + ch * 4);
        }
        CP_COMMIT();
        int tk2b = (((p0 + 1) & (kNIt - 1)) * kTileK2);
#pragma unroll
        for (int h = 0; h < 4; h++) {
            int q = tid + h * kThreads;
            int col = q >> 3, ch = q & 7;
            cp_async16(smW + kWTileU + col * kWStrideU + ch * 4,
                       g_WbT + col * kK2 + tk2b + ch * 4);
        }
        CP_COMMIT();
    }
#pragma unroll
    for (int h = 0; h < 4; h++) {
        int q = tid + h * kThreads;
        if (q < 2048) {
            int r  = q >> 6;
            int ch = q & 63;
            int gr = row0 + r;
            float4 f0 = make_float4(0.f, 0.f, 0.f, 0.f);
            float4 f1 = f0;
            if (gr <= kT) {
                const float4* src = (const float4*)(s_i + gr * kS + ch * 8);
                f0 = src[0];
                f1 = src[1];
            }
            uint4 pk;
            pk.x = pack_bf16(f0.x, f0.y);
            pk.y = pack_bf16(f0.z, f0.w);
            pk.z = pack_bf16(f1.x, f1.y);
            pk.w = pack_bf16(f1.z, f1.w);
            *(uint4*)(smA + r * kAStrideU + ch * 4) = pk;
        }
    }

    // ---- Phase 1b: bf16 tensor-core GEMM (M=32: two 16-row groups) ----
    const int lane = tid & 31;
    const int wid  = tid >> 5;
    const int g    = lane >> 2;
    const int t    = lane & 3;
    const int cb0  = wid * 16;
    const int cb1  = cb0 + 8;

    float c0[4] = {0.f, 0.f, 0.f, 0.f};
    float c1[4] = {0.f, 0.f, 0.f, 0.f};
    float c2[4] = {0.f, 0.f, 0.f, 0.f};
    float c3[4] = {0.f, 0.f, 0.f, 0.f};

    for (int i = 0; i < kNIt; i++) {
        if (i == kNIt - 1) { CP_WAIT0(); } else { CP_WAIT1(); }
        __syncthreads();
        if (i + 2 < kNIt) {
            u32* d = smW + ((i + 2) % 3) * kWTileU;
            int tk2 = (((p0 + i + 2) & (kNIt - 1)) * kTileK2);
#pragma unroll
            for (int h = 0; h < 4; h++) {
                int q = tid + h * kThreads;
                int col = q >> 3, ch = q & 7;
                cp_async16(d + col * kWStrideU + ch * 4,
                           g_WbT + col * kK2 + tk2 + ch * 4);
            }
            CP_COMMIT();
        }
        const int phys = (p0 + i) & (kNIt - 1);
        const u32* wt = smW + (i % 3) * kWTileU;
        const int kb2 = phys * kTileK2;
#pragma unroll
        for (int kk = 0; kk < 4; kk++) {
            const int o  = kb2 + kk * 8;
            const int ot = kk * 8;
            u32 a0 = smA[(g     ) * kAStrideU + o + t    ];
            u32 a1 = smA[(g +  8) * kAStrideU + o + t    ];
            u32 a2 = smA[(g     ) * kAStrideU + o + t + 4];
            u32 a3 = smA[(g +  8) * kAStrideU + o + t + 4];
            u32 d0 = smA[(g + 16) * kAStrideU + o + t    ];
            u32 d1 = smA[(g + 24) * kAStrideU + o + t    ];
            u32 d2 = smA[(g + 16) * kAStrideU + o + t + 4];
            u32 d3 = smA[(g + 24) * kAStrideU + o + t + 4];
            u32 b00 = wt[(cb0 + g) * kWStrideU + ot + t    ];
            u32 b01 = wt[(cb0 + g) * kWStrideU + ot + t + 4];
            u32 b10 = wt[(cb1 + g) * kWStrideU + ot + t    ];
            u32 b11 = wt[(cb1 + g) * kWStrideU + ot + t + 4];
            mma_bf16(c0, a0, a1, a2, a3, b00, b01);
            mma_bf16(c1, a0, a1, a2, a3, b10, b11);
            mma_bf16(c2, d0, d1, d2, d3, b00, b01);
            mma_bf16(c3, d0, d1, d2, d3, b10, b11);
        }
    }
    __syncthreads();

    // ---- Phase 1c: epilogue — scatter C fragments to smL[r*336 + c] ----
    {
        int col0 = cb0 + 2 * t;
        int col1 = cb1 + 2 * t;
        smL[(g     ) * kColsTot + col0    ] = c0[0];
        smL[(g     ) * kColsTot + col0 + 1] = c0[1];
        smL[(g +  8) * kColsTot + col0    ] = c0[2];
        smL[(g +  8) * kColsTot + col0 + 1] = c0[3];
        smL[(g     ) * kColsTot + col1    ] = c1[0];
        smL[(g     ) * kColsTot + col1 + 1] = c1[1];
        smL[(g +  8) * kColsTot + col1    ] = c1[2];
        smL[(g +  8) * kColsTot + col1 + 1] = c1[3];
        smL[(g + 16) * kColsTot + col0    ] = c2[0];
        smL[(g + 16) * kColsTot + col0 + 1] = c2[1];
        smL[(g + 24) * kColsTot + col0    ] = c2[2];
        smL[(g + 24) * kColsTot + col0 + 1] = c2[3];
        smL[(g + 16) * kColsTot + col1    ] = c3[0];
        smL[(g + 16) * kColsTot + col1 + 1] = c3[1];
        smL[(g + 24) * kColsTot + col1    ] = c3[2];
        smL[(g + 24) * kColsTot + col1 + 1] = c3[3];
    }
    __syncthreads();

    // ---- Phase 1d: softmaxes (512 threads: r = tid>>4, b = tid&15) ----
    if (tid < 512) {
        const int r = tid >> 4;
        const int b = tid & 15;
        const int i = row0 + r;
        const bool valid = (i <= kT);
        const int is64 = s_is64;

        if (valid) {
            if (i < kT) {
                int a;
                if (is64) a = (int)((const long long*)actions_raw)[i];
                else      a = ((const int*)actions_raw)[i];
                const float* L = &smL[r * kColsTot + b * kA];
                float m = L[0];
#pragma unroll
                for (int j = 1; j < kA; j++) m = fmaxf(m, L[j]);
                float s = 0.0f;
#pragma unroll
                for (int j = 0; j < kA; j++) s += __expf(L[j] - m);
                sEa[r * kB + b] = __expf(L[a] - m) / s;
            }
            float x0 = smL[r * kColsTot + 288 + 2 * b];
            float x1 = smL[r * kColsTot + 288 + 2 * b + 1];
            float m = fmaxf(x0, x1);
            float e0 = __expf(x0 - m), e1 = __expf(x1 - m);
            float inv = 1.0f / (e0 + e1);
            float es0 = e0 * inv;
            sE0[r * kB + b] = es0;
            sE1[r * kB + b] = e1 * inv;
            if (i == kT) { g_es0_fin[b] = es0; __threadfence(); }
        }
        {
            float x = smL[r * kColsTot + 320 + b];
            float m = x;
            m = fmaxf(m, __shfl_xor_sync(0xFFFFFFFFu, m, 1));
            m = fmaxf(m, __shfl_xor_sync(0xFFFFFFFFu, m, 2));
            m = fmaxf(m, __shfl_xor_sync(0xFFFFFFFFu, m, 4));
            m = fmaxf(m, __shfl_xor_sync(0xFFFFFFFFu, m, 8));
            float e = __expf(x - m);
            float s = e;
            s += __shfl_xor_sync(0xFFFFFFFFu, s, 1);
            s += __shfl_xor_sync(0xFFFFFFFFu, s, 2);
            s += __shfl_xor_sync(0xFFFFFFFFu, s, 4);
            s += __shfl_xor_sync(0xFFFFFFFFu, s, 8);
            if (valid) sEs[r * kB + b] = e / s;
        }
    }
    __syncthreads();

    // ---- Phase 2: compose 2 windows in parallel (warps 0,1) + y ----
    if (blk < kNB2 && tid < 64) {
        const int w   = tid >> 5;        // window within block
        const int k   = tid & 15;
        const int sb  = w * kBlkSteps;   // step base in smem arrays
        float P16[16];
#pragma unroll
        for (int j = 0; j < 16; j++) P16[j] = (j == k) ? 1.0f : 0.0f;
        for (int s = 0; s < kBlkSteps; s++) {
            if (!(blk == 0 && w == 0 && s == 0)) {
                float s0[16], s1[16], vv[16];
                load16s(s0, &sE0[(sb + s) * kB]);
                load16s(s1, &sE1[(sb + s) * kB]);
                load16s(vv, &sEs[(sb + s) * kB]);
                float m[16];
#pragma unroll
                for (int j = 0; j < 16; j++) m[j] = s1[j] * P16[j];
                float wsum = tree16(m);
#pragma unroll
                for (int j = 0; j < 16; j++)
                    P16[j] = fmaf(s0[j], P16[j], (vv[j] * EXP_NEG_PEN) * wsum);
            }
            float ea[16];
            load16s(ea, &sEa[(sb + s) * kB]);
            float m2[16];
#pragma unroll
            for (int j = 0; j < 16; j++) m2[j] = ea[j] * P16[j];
            float y = tree16(m2);
            if ((tid & 31) < 16) sY[(sb + s) * kB + k] = y;
        }
        if ((tid & 31) < 16) {
            const int win = blk * 2 + w;
#pragma unroll
            for (int j = 0; j < 16; j++)
                g_M[win * 256 + j * 16 + k] = P16[j];
        }
        __threadfence();
        __syncwarp();
        if ((tid & 31) == 0) atomicAdd(&g_mcnt, 1u);
    }

    // ---- Phase 3: serial scan (block 0 waits for all 128 windows) ----
    if (blk == 0) {
        if (tid == 0) {
            volatile unsigned* vm = &g_mcnt;
            while (*vm < (unsigned)kNWin) { __nanosleep(64); }
            g_mcnt = 0;
            __threadfence();
        }
        __syncthreads();

        float* smM = (float*)smem;   // [0, 40960) — GEMM data dead here
#pragma unroll
        for (int h = 0; h < 13; h++) {
            int q = tid + h * kThreads;
            if (q < 8192) {
                int m   = q >> 6;
                int rem = q & 63;
                int row = rem >> 2;
                int ch  = rem & 3;
                cp_async16(smM + m * kMStrideMat + row * kMStrideRow + ch * 4,
                           (const float*)g_M + q * 4);
            }
        }
        CP_COMMIT();
        CP_WAIT0();
        __syncthreads();

        if (tid < 32) {
            const int r = tid & 15;
            float Q[16];
            load16s(Q, &sEs[0]);     // block 0 owns row 0 (start softmax)
            if (tid < 16) g_chk[tid] = Q[tid];
            if (tid == 0) g_Eb[0] = 0;
            int E = 0;

            const float* Mr = smM + r * kMStrideRow;
            float4 a0 = *(const float4*)(Mr + 0);
            float4 a1 = *(const float4*)(Mr + 4);
            float4 a2 = *(const float4*)(Mr + 8);
            float4 a3 = *(const float4*)(Mr + 12);

            for (int j = 0; j < kNWin; j++) {
                float4 b0, b1, b2, b3;
                if (j + 1 < kNWin) {
                    const float* Mn = smM + (j + 1) * kMStrideMat + r * kMStrideRow;
                    b0 = *(const float4*)(Mn + 0);
                    b1 = *(const float4*)(Mn + 4);
                    b2 = *(const float4*)(Mn + 8);
                    b3 = *(const float4*)(Mn + 12);
                }
                float mm[16] = {a0.x, a0.y, a0.z, a0.w, a1.x, a1.y, a1.z, a1.w,
                                a2.x, a2.y, a2.z, a2.w, a3.x, a3.y, a3.z, a3.w};
                float pr[16];
#pragma unroll
                for (int kk = 0; kk < 16; kk++) pr[kk] = mm[kk] * Q[kk];
                float outr = tree16(pr);

                float Qn[16];
#pragma unroll
                for (int kk = 0; kk < 16; kk++)
                    Qn[kk] = __shfl_sync(0xFFFFFFFFu, outr, kk);

                if ((j & 3) == 3) {
                    float ss = tree16(Qn);
                    int e = ((__float_as_int(ss) >> 23) & 0xFF) - 127;
                    float sc = __int_as_float((127 - e) << 23);
#pragma unroll
                    for (int kk = 0; kk < 16; kk++) Q[kk] = Qn[kk] * sc;
                    E += e;
                } else {
#pragma unroll
                    for (int kk = 0; kk < 16; kk++) Q[kk] = Qn[kk];
                }

                if (tid < 16) g_chk[(j + 1) * kB + tid] = Q[tid];
                if (tid == 0) g_Eb[j + 1] = E;
                a0 = b0; a1 = b1; a2 = b2; a3 = b3;
            }
            __threadfence();
        }
    }

    gbar(0, kGrid);   // checkpoints ready

    // ---- Phase 4: y-dot tot (32 threads/block, 2 windows) + reduction ----
    if (blk < kNB2) {
        if (tid < 32) {
            const int win = blk * 2 + (tid >> 4);
            float c[16];
            load16g(c, &g_chk[win * kB]);
            const int E = __ldcg(&g_Eb[win]);
            float y[16];
            load16s(y, &sY[tid * kB]);
            float pr[16];
#pragma unroll
            for (int kk = 0; kk < 16; kk++) pr[kk] = y[kk] * c[kk];
            float u = tree16(pr);
            double acc = (double)__logf(u) + (double)E * LN2;

#pragma unroll
            for (int o = 16; o > 0; o >>= 1)
                acc += __shfl_down_sync(0xFFFFFFFFu, acc, o);

            if (tid == 0) {
                atomicAdd(&g_tot, acc);
                __threadfence();
                unsigned old = atomicAdd(&g_rcnt, 1u);
                if (old == (unsigned)(kGrid - 1)) {
                    __threadfence();
                    double v = atomicAdd(&g_tot, 0.0);
                    out[0] = (float)v;
                    g_rcnt = 0u;
                    g_tot = 0.0;
                    __threadfence();
                }
            }
        }
    } else {
        // block 64: final stop term
        if (tid == 0) {
            float f[16], cf[16];
            load16g(f, g_es0_fin);
            load16g(cf, &g_chk[kNWin * kB]);
            float p2[16];
#pragma unroll
            for (int kk = 0; kk < 16; kk++) p2[kk] = f[kk] * cf[kk];
            float uf = tree16(p2);
            double acc = (double)__logf(uf) + (double)__ldcg(&g_Eb[kNWin]) * LN2;
            atomicAdd(&g_tot, acc);
            __threadfence();
            unsigned old = atomicAdd(&g_rcnt, 1u);
            if (old == (unsigned)(kGrid - 1)) {
                __threadfence();
                double v = atomicAdd(&g_tot, 0.0);
                out[0] = (float)v;
                g_rcnt = 0u;
                g_tot = 0.0;
                __threadfence();
            }
        }
    }
}

// ---------------------------------------------------------------------------
// Launch
// ---------------------------------------------------------------------------
extern "C" void kernel_launch(void* const* d_in, const int* in_sizes, int n_in,
                              void* d_out, int out_size) {
    const float* s_i = (const float*)d_in[0];
    const float* Wa  = (const float*)d_in[1];
    const float* Wsp = (const float*)d_in[2];
    const float* Wst = (const float*)d_in[3];
    const void*  act = d_in[4];

    cudaFuncSetAttribute(fused_kernel,
                         cudaFuncAttributeMaxDynamicSharedMemorySize,
                         kSmemBytes);

    convert_w_kernel<<<(kColsTot * kK2 + 255) / 256, 256>>>(Wa, Wsp, Wst);
    fused_kernel<<<kGrid, kThreads, kSmemBytes>>>(s_i, act, (float*)d_out);
}

// round 16
// speedup vs baseline: 1.0221x; 1.0221x over previous
#include <cuda_runtime.h>
#include <cuda_bf16.h>

typedef unsigned int u32;

// ---------------------------------------------------------------------------
// Problem constants
// ---------------------------------------------------------------------------
namespace {
constexpr int kT = 2048;
constexpr int kS = 512;
constexpr int kB = 16;
constexpr int kA = 18;
constexpr int kColsTot = 336;           // 288 + 32 + 16
constexpr int kRowsPerBlk = 16;
constexpr int kBlkSteps = 16;
constexpr int kNBlks = 128;
constexpr int kGrid = 129;
constexpr int kThreads = 672;           // 21 warps
constexpr int kK2 = 256;                // k-pairs (bf16x2 along K)
constexpr int kAStrideU = 260;          // smA row stride (u32)
constexpr int kWStrideU = 36;           // smW col stride (u32)
constexpr int kTileK2 = 32;             // k-pairs per W tile
constexpr int kNIt = 8;
constexpr int kWTileU = kColsTot * kWStrideU;   // 12096
// smem layout (u32 units)
constexpr int kOffA  = 0;                        // 16*260 = 4160
constexpr int kOffW  = 4160;                     // 3 tiles -> 40448
// serial-phase M cache spans [0, 40960)
constexpr int kOffE0 = 41984;
constexpr int kOffE1 = kOffE0 + 256;
constexpr int kOffEs = kOffE1 + 256;
constexpr int kOffEa = kOffEs + 256;
constexpr int kOffY  = kOffEa + 256;             // y vectors 16x16
constexpr int kSmemU = kOffY + 256;              // 43264
constexpr int kSmemBytes = kSmemU * 4;           // 173056
constexpr int kMStrideRow = 20;
constexpr int kMStrideMat = 320;
}
#define EXP_NEG_PEN 0.60653065971263342f
#define LN2 0.69314718055994530942

// Cross-kernel / cross-block scratch.
__device__ u32    g_WbT[kColsTot * kK2];   // W transposed, bf16x2, k-interleaved
__device__ float  g_M[kNBlks * 256];
__device__ float  g_chk[(kNBlks + 1) * kB];
__device__ int    g_Eb[kNBlks + 1];
__device__ float  g_es0_fin[kB];
__device__ double g_tot;
__device__ unsigned g_mcnt;
__device__ unsigned g_rcnt;

struct Bar { unsigned cnt; unsigned gen; };
__device__ Bar g_bars[2];

__device__ __forceinline__ void gbar(int id, unsigned nb) {
    __syncthreads();
    if (threadIdx.x == 0) {
        __threadfence();
        volatile unsigned* vgen = &g_bars[id].gen;
        unsigned g0 = *vgen;
        unsigned prev = atomicAdd(&g_bars[id].cnt, 1u);
        if (prev == nb - 1u) {
            g_bars[id].cnt = 0u;
            __threadfence();
            atomicAdd(&g_bars[id].gen, 1u);
        } else {
            while (*vgen == g0) { __nanosleep(64); }
            __threadfence();
        }
    }
    __syncthreads();
}

// ---------------------------------------------------------------------------
// helpers
// ---------------------------------------------------------------------------
__device__ __forceinline__ void cp_async16(void* sdst, const void* gsrc) {
    unsigned a = (unsigned)__cvta_generic_to_shared(sdst);
    asm volatile("cp.async.cg.shared.global [%0], [%1], 16;" :: "r"(a), "l"(gsrc));
}
#define CP_COMMIT() asm volatile("cp.async.commit_group;")
#define CP_WAIT1()  asm volatile("cp.async.wait_group 1;")
#define CP_WAIT0()  asm volatile("cp.async.wait_group 0;")

__device__ __forceinline__ u32 pack_bf16(float lo, float hi) {
    unsigned short l = __bfloat16_as_ushort(__float2bfloat16_rn(lo));
    unsigned short h = __bfloat16_as_ushort(__float2bfloat16_rn(hi));
    return ((u32)h << 16) | (u32)l;
}
__device__ __forceinline__ void mma_bf16(float c[4], u32 a0, u32 a1, u32 a2,
                                         u32 a3, u32 b0, u32 b1) {
    asm("mma.sync.aligned.m16n8k16.row.col.f32.bf16.bf16.f32 "
        "{%0,%1,%2,%3},{%4,%5,%6,%7},{%8,%9},{%0,%1,%2,%3};"
        : "+f"(c[0]), "+f"(c[1]), "+f"(c[2]), "+f"(c[3])
        : "r"(a0), "r"(a1), "r"(a2), "r"(a3), "r"(b0), "r"(b1));
}
__device__ __forceinline__ void load16s(float d[16], const float* p) {
    const float4* p4 = (const float4*)p;
    float4 a = p4[0], b = p4[1], c = p4[2], e = p4[3];
    d[0]=a.x; d[1]=a.y; d[2]=a.z; d[3]=a.w;
    d[4]=b.x; d[5]=b.y; d[6]=b.z; d[7]=b.w;
    d[8]=c.x; d[9]=c.y; d[10]=c.z; d[11]=c.w;
    d[12]=e.x; d[13]=e.y; d[14]=e.z; d[15]=e.w;
}
__device__ __forceinline__ void load16g(float d[16], const float* p) {
    float4 a = __ldcg((const float4*)p);
    float4 b = __ldcg((const float4*)p + 1);
    float4 c = __ldcg((const float4*)p + 2);
    float4 e = __ldcg((const float4*)p + 3);
    d[0]=a.x; d[1]=a.y; d[2]=a.z; d[3]=a.w;
    d[4]=b.x; d[5]=b.y; d[6]=b.z; d[7]=b.w;
    d[8]=c.x; d[9]=c.y; d[10]=c.z; d[11]=c.w;
    d[12]=e.x; d[13]=e.y; d[14]=e.z; d[15]=e.w;
}
__device__ __forceinline__ float tree16(const float v[16]) {
    float a0=v[0]+v[1], a1=v[2]+v[3], a2=v[4]+v[5], a3=v[6]+v[7];
    float a4=v[8]+v[9], a5=v[10]+v[11], a6=v[12]+v[13], a7=v[14]+v[15];
    float b0=a0+a1, b1=a2+a3, b2=a4+a5, b3=a6+a7;
    return (b0+b1)+(b2+b3);
}

// ---------------------------------------------------------------------------
// K0: convert W -> transposed bf16 pairs, k-interleaved within 8-groups:
// position order per group = (0,4,1,5,2,6,3,7) so fragment pairs {t, t+4}
// land adjacent (enables LDS.64 in the MMA loop).
// ---------------------------------------------------------------------------
__global__ __launch_bounds__(256) void convert_w_kernel(
    const float* __restrict__ Wa,
    const float* __restrict__ Wsp,
    const float* __restrict__ Wst) {
    int idx = blockIdx.x * 256 + threadIdx.x;
    if (idx >= kColsTot * kK2) return;
    int k2 = idx / kColsTot;
    int col = idx - k2 * kColsTot;
    const float* base; int stride, off;
    if (col < 288)      { base = Wa;  stride = 288; off = col; }
    else if (col < 320) { base = Wsp; stride = 32;  off = col - 288; }
    else                { base = Wst; stride = 16;  off = col - 320; }
    float x0 = base[(2 * k2    ) * stride + off];
    float x1 = base[(2 * k2 + 1) * stride + off];
    int j = k2 & 7;
    int pos = (k2 & ~7) | ((j < 4) ? (2 * j) : (2 * (j - 4) + 1));
    g_WbT[col * kK2 + pos] = pack_bf16(x0, x1);
}

// ---------------------------------------------------------------------------
// K1: fused — A-pack (interleaved), GEMM (LDS.64 fragments), softmax,
//     compose(+y), serial scan, y-dot tot
// ---------------------------------------------------------------------------
__global__ __launch_bounds__(kThreads) void fused_kernel(
    const float* __restrict__ s_i,
    const void* __restrict__ actions_raw,
    float* __restrict__ out) {
    extern __shared__ __align__(16) u32 smem[];
    u32* smA = smem + kOffA;
    u32* smW = smem + kOffW;
    float* smL = (float*)(smem + kOffW);     // logits alias W buf0 after GEMM
    float* sE0 = (float*)(smem + kOffE0);
    float* sE1 = (float*)(smem + kOffE1);
    float* sEs = (float*)(smem + kOffEs);
    float* sEa = (float*)(smem + kOffEa);
    float* sY  = (float*)(smem + kOffY);
    __shared__ int s_is64;

    const int tid  = threadIdx.x;
    const int blk  = blockIdx.x;
    const int row0 = blk * kRowsPerBlk;

    if (tid == 0) {
        const unsigned* w = (const unsigned*)actions_raw;
        unsigned acc = 0;
#pragma unroll
        for (int j = 1; j < 64; j += 2) acc |= w[j];
        s_is64 = (acc == 0u) ? 1 : 0;
    }

    // ---- Phase 1a: W prestage (tiles p0, p0+1) + interleaved A-pack ----
    const int p0 = blk & (kNIt - 1);
    {
        int tk2 = p0 * kTileK2;
#pragma unroll
        for (int h = 0; h < 4; h++) {
            int q = tid + h * kThreads;
            int col = q >> 3, ch = q & 7;
            cp_async16(smW + col * kWStrideU + ch * 4,
                       g_WbT + col * kK2 + tk2 + ch * 4);
        }
        CP_COMMIT();
        int tk2b = (((p0 + 1) & (kNIt - 1)) * kTileK2);
#pragma unroll
        for (int h = 0; h < 4; h++) {
            int q = tid + h * kThreads;
            int col = q >> 3, ch = q & 7;
            cp_async16(smW + kWTileU + col * kWStrideU + ch * 4,
                       g_WbT + col * kK2 + tk2b + ch * 4);
        }
        CP_COMMIT();
    }
    // A-pack with the same k-interleaving: memory positions ch*4..ch*4+3 hold
    // k2 = {b, b+4, b+1, b+5} where b = (ch>>1)*8 + (ch&1)*2.
#pragma unroll
    for (int h = 0; h < 2; h++) {
        int q = tid + h * kThreads;
        if (q < 1024) {
            int r  = q >> 6;
            int ch = q & 63;
            int gr = row0 + r;
            int fo = (ch >> 1) * 16 + (ch & 1) * 4;   // float offset of k2 b
            float4 f0 = make_float4(0.f, 0.f, 0.f, 0.f);
            float4 f1 = f0;
            if (gr <= kT) {
                const float* src = s_i + gr * kS + fo;
                f0 = *(const float4*)src;          // k2 b, b+1
                f1 = *(const float4*)(src + 8);    // k2 b+4, b+5
            }
            uint4 pk;
            pk.x = pack_bf16(f0.x, f0.y);   // k2 b
            pk.y = pack_bf16(f1.x, f1.y);   // k2 b+4
            pk.z = pack_bf16(f0.z, f0.w);   // k2 b+1
            pk.w = pack_bf16(f1.z, f1.w);   // k2 b+5
            *(uint4*)(smA + r * kAStrideU + ch * 4) = pk;
        }
    }

    // ---- Phase 1b: bf16 tensor-core GEMM (LDS.64 fragment loads) ----
    const int lane = tid & 31;
    const int wid  = tid >> 5;
    const int g    = lane >> 2;
    const int t    = lane & 3;
    const int cb0  = wid * 16;
    const int cb1  = cb0 + 8;

    float c0[4] = {0.f, 0.f, 0.f, 0.f};
    float c1[4] = {0.f, 0.f, 0.f, 0.f};

    for (int i = 0; i < kNIt; i++) {
        if (i == kNIt - 1) { CP_WAIT0(); } else { CP_WAIT1(); }
        __syncthreads();
        if (i + 2 < kNIt) {
            u32* d = smW + ((i + 2) % 3) * kWTileU;
            int tk2 = (((p0 + i + 2) & (kNIt - 1)) * kTileK2);
#pragma unroll
            for (int h = 0; h < 4; h++) {
                int q = tid + h * kThreads;
                int col = q >> 3, ch = q & 7;
                cp_async16(d + col * kWStrideU + ch * 4,
                           g_WbT + col * kK2 + tk2 + ch * 4);
            }
            CP_COMMIT();
        }
        const int phys = (p0 + i) & (kNIt - 1);
        const u32* wt = smW + (i % 3) * kWTileU;
        const int kb2 = phys * kTileK2;
#pragma unroll
        for (int kk = 0; kk < 4; kk++) {
            const int op = kb2 + kk * 8 + 2 * t;    // A position offset
            const int wp = kk * 8 + 2 * t;          // W position offset
            uint2 A0 = *(const uint2*)(smA + (g    ) * kAStrideU + op); // a0,a2
            uint2 A1 = *(const uint2*)(smA + (g + 8) * kAStrideU + op); // a1,a3
            uint2 B0 = *(const uint2*)(wt + (cb0 + g) * kWStrideU + wp);
            uint2 B1 = *(const uint2*)(wt + (cb1 + g) * kWStrideU + wp);
            mma_bf16(c0, A0.x, A1.x, A0.y, A1.y, B0.x, B0.y);
            mma_bf16(c1, A0.x, A1.x, A0.y, A1.y, B1.x, B1.y);
        }
    }
    __syncthreads();

    // ---- Phase 1c: epilogue — scatter C fragments to smL[r*336 + c] ----
    {
        int col0 = cb0 + 2 * t;
        smL[(g    ) * kColsTot + col0    ] = c0[0];
        smL[(g    ) * kColsTot + col0 + 1] = c0[1];
        smL[(g + 8) * kColsTot + col0    ] = c0[2];
        smL[(g + 8) * kColsTot + col0 + 1] = c0[3];
        int col1 = cb1 + 2 * t;
        smL[(g    ) * kColsTot + col1    ] = c1[0];
        smL[(g    ) * kColsTot + col1 + 1] = c1[1];
        smL[(g + 8) * kColsTot + col1    ] = c1[2];
        smL[(g + 8) * kColsTot + col1 + 1] = c1[3];
    }
    __syncthreads();

    // ---- Phase 1d: softmaxes ----
    if (tid < 256) {
        const int r = tid >> 4;
        const int b = tid & 15;
        const int i = row0 + r;
        const bool valid = (i <= kT);
        const int is64 = s_is64;

        if (valid) {
            if (i < kT) {
                int a;
                if (is64) a = (int)((const long long*)actions_raw)[i];
                else      a = ((const int*)actions_raw)[i];
                const float* L = &smL[r * kColsTot + b * kA];
                float m = L[0];
#pragma unroll
                for (int j = 1; j < kA; j++) m = fmaxf(m, L[j]);
                float s = 0.0f;
#pragma unroll
                for (int j = 0; j < kA; j++) s += __expf(L[j] - m);
                sEa[r * kB + b] = __expf(L[a] - m) / s;
            }
            float x0 = smL[r * kColsTot + 288 + 2 * b];
            float x1 = smL[r * kColsTot + 288 + 2 * b + 1];
            float m = fmaxf(x0, x1);
            float e0 = __expf(x0 - m), e1 = __expf(x1 - m);
            float inv = 1.0f / (e0 + e1);
            float es0 = e0 * inv;
            sE0[r * kB + b] = es0;
            sE1[r * kB + b] = e1 * inv;
            if (i == kT) { g_es0_fin[b] = es0; __threadfence(); }
        }
        {
            float x = smL[r * kColsTot + 320 + b];
            float m = x;
            m = fmaxf(m, __shfl_xor_sync(0xFFFFFFFFu, m, 1));
            m = fmaxf(m, __shfl_xor_sync(0xFFFFFFFFu, m, 2));
            m = fmaxf(m, __shfl_xor_sync(0xFFFFFFFFu, m, 4));
            m = fmaxf(m, __shfl_xor_sync(0xFFFFFFFFu, m, 8));
            float e = __expf(x - m);
            float s = e;
            s += __shfl_xor_sync(0xFFFFFFFFu, s, 1);
            s += __shfl_xor_sync(0xFFFFFFFFu, s, 2);
            s += __shfl_xor_sync(0xFFFFFFFFu, s, 4);
            s += __shfl_xor_sync(0xFFFFFFFFu, s, 8);
            if (valid) sEs[r * kB + b] = e / s;
        }
    }
    __syncthreads();

    // ---- Phase 2: compose (+ y into smem); signal g_mcnt ----
    if (blk < kNBlks && tid < 32) {
        const int k = tid & 15;
        float P16[16];
#pragma unroll
        for (int j = 0; j < 16; j++) P16[j] = (j == k) ? 1.0f : 0.0f;
        for (int s = 0; s < kBlkSteps; s++) {
            if (!(blk == 0 && s == 0)) {
                float s0[16], s1[16], vv[16];
                load16s(s0, &sE0[s * kB]);
                load16s(s1, &sE1[s * kB]);
                load16s(vv, &sEs[s * kB]);
                float m[16];
#pragma unroll
                for (int j = 0; j < 16; j++) m[j] = s1[j] * P16[j];
                float w = tree16(m);
#pragma unroll
                for (int j = 0; j < 16; j++)
                    P16[j] = fmaf(s0[j], P16[j], (vv[j] * EXP_NEG_PEN) * w);
            }
            float ea[16];
            load16s(ea, &sEa[s * kB]);
            float m2[16];
#pragma unroll
            for (int j = 0; j < 16; j++) m2[j] = ea[j] * P16[j];
            float y = tree16(m2);
            if (tid < 16) sY[s * kB + k] = y;
        }
        if (tid < 16) {
#pragma unroll
            for (int j = 0; j < 16; j++)
                g_M[blk * 256 + j * 16 + k] = P16[j];
        }
        __threadfence();
        __syncwarp();
        if (tid == 0) atomicAdd(&g_mcnt, 1u);
    }

    // ---- Phase 3: serial scan (block 0 only waits for M) ----
    if (blk == 0) {
        if (tid == 0) {
            volatile unsigned* vm = &g_mcnt;
            while (*vm < (unsigned)kNBlks) { __nanosleep(64); }
            g_mcnt = 0;
            __threadfence();
        }
        __syncthreads();

        float* smM = (float*)smem;   // 128 matrices, stride 320, ends 40960
#pragma unroll
        for (int h = 0; h < 13; h++) {
            int q = tid + h * kThreads;
            if (q < 8192) {
                int m   = q >> 6;
                int rem = q & 63;
                int row = rem >> 2;
                int ch  = rem & 3;
                cp_async16(smM + m * kMStrideMat + row * kMStrideRow + ch * 4,
                           (const float*)g_M + q * 4);
            }
        }
        CP_COMMIT();
        CP_WAIT0();
        __syncthreads();

        if (tid < 32) {
            const int r = tid & 15;
            float Q[16];
            load16s(Q, &sEs[0]);     // block 0 owns row 0 (start softmax)
            if (tid < 16) g_chk[tid] = Q[tid];
            if (tid == 0) g_Eb[0] = 0;
            int E = 0;

            const float* Mr = smM + r * kMStrideRow;
            float4 a0 = *(const float4*)(Mr + 0);
            float4 a1 = *(const float4*)(Mr + 4);
            float4 a2 = *(const float4*)(Mr + 8);
            float4 a3 = *(const float4*)(Mr + 12);

            for (int j = 0; j < kNBlks; j++) {
                float4 b0, b1, b2, b3;
                if (j + 1 < kNBlks) {
                    const float* Mn = smM + (j + 1) * kMStrideMat + r * kMStrideRow;
                    b0 = *(const float4*)(Mn + 0);
                    b1 = *(const float4*)(Mn + 4);
                    b2 = *(const float4*)(Mn + 8);
                    b3 = *(const float4*)(Mn + 12);
                }
                float mm[16] = {a0.x, a0.y, a0.z, a0.w, a1.x, a1.y, a1.z, a1.w,
                                a2.x, a2.y, a2.z, a2.w, a3.x, a3.y, a3.z, a3.w};
                float pr[16];
#pragma unroll
                for (int kk = 0; kk < 16; kk++) pr[kk] = mm[kk] * Q[kk];
                float outr = tree16(pr);

                float Qn[16];
#pragma unroll
                for (int kk = 0; kk < 16; kk++)
                    Qn[kk] = __shfl_sync(0xFFFFFFFFu, outr, kk);

                if ((j & 3) == 3) {
                    float ss = tree16(Qn);
                    int e = ((__float_as_int(ss) >> 23) & 0xFF) - 127;
                    float sc = __int_as_float((127 - e) << 23);
#pragma unroll
                    for (int kk = 0; kk < 16; kk++) Q[kk] = Qn[kk] * sc;
                    E += e;
                } else {
#pragma unroll
                    for (int kk = 0; kk < 16; kk++) Q[kk] = Qn[kk];
                }

                if (tid < 16) g_chk[(j + 1) * kB + tid] = Q[tid];
                if (tid == 0) g_Eb[j + 1] = E;
                a0 = b0; a1 = b1; a2 = b2; a3 = b3;
            }
            __threadfence();
        }
    }

    gbar(0, kGrid);   // checkpoints ready

    // ---- Phase 4: y-dot tot (16 threads/block) + atomic reduction ----
    if (blk < kNBlks && tid < 16) {
        float c[16];
        load16g(c, &g_chk[blk * kB]);
        const int E = __ldcg(&g_Eb[blk]);
        float y[16];
        load16s(y, &sY[tid * kB]);      // this thread's step
        float pr[16];
#pragma unroll
        for (int kk = 0; kk < 16; kk++) pr[kk] = y[kk] * c[kk];
        float u = tree16(pr);
        double acc = (double)__logf(u);

#pragma unroll
        for (int o = 8; o > 0; o >>= 1)
            acc += __shfl_down_sync(0x0000FFFFu, acc, o, 16);

        if (tid == 0) {
            acc += (double)(kBlkSteps * E) * LN2;
            if (blk == kNBlks - 1) {
                float f[16], cf[16];
                load16g(f, g_es0_fin);
                load16g(cf, &g_chk[kNBlks * kB]);
                float p2[16];
#pragma unroll
                for (int kk = 0; kk < 16; kk++) p2[kk] = f[kk] * cf[kk];
                float uf = tree16(p2);
                acc += (double)__logf(uf) + (double)__ldcg(&g_Eb[kNBlks]) * LN2;
            }
            atomicAdd(&g_tot, acc);
            __threadfence();
            unsigned old = atomicAdd(&g_rcnt, 1u);
            if (old == (unsigned)(kNBlks - 1)) {
                __threadfence();
                double v = atomicAdd(&g_tot, 0.0);
                out[0] = (float)v;
                g_rcnt = 0u;
                g_tot = 0.0;
                __threadfence();
            }
        }
    }
}

// ---------------------------------------------------------------------------
// Launch
// ---------------------------------------------------------------------------
extern "C" void kernel_launch(void* const* d_in, const int* in_sizes, int n_in,
                              void* d_out, int out_size) {
    const float* s_i = (const float*)d_in[0];
    const float* Wa  = (const float*)d_in[1];
    const float* Wsp = (const float*)d_in[2];
    const float* Wst = (const float*)d_in[3];
    const void*  act = d_in[4];

    cudaFuncSetAttribute(fused_kernel,
                         cudaFuncAttributeMaxDynamicSharedMemorySize,
                         kSmemBytes);

    convert_w_kernel<<<(kColsTot * kK2 + 255) / 256, 256>>>(Wa, Wsp, Wst);
    fused_kernel<<<kGrid, kThreads, kSmemBytes>>>(s_i, act, (float*)d_out);
}

// round 17
// speedup vs baseline: 1.1598x; 1.1347x over previous
#include <cuda_runtime.h>
#include <cuda_bf16.h>

typedef unsigned int u32;

// ---------------------------------------------------------------------------
// Problem constants
// ---------------------------------------------------------------------------
namespace {
constexpr int kT = 2048;
constexpr int kS = 512;
constexpr int kB = 16;
constexpr int kA = 18;
constexpr int kColsTot = 336;           // 288 + 32 + 16
constexpr int kRowsPerBlk = 16;
constexpr int kBlkSteps = 16;
constexpr int kNBlks = 128;
constexpr int kGrid = 129;
constexpr int kThreads = 672;           // 21 warps
constexpr int kK2 = 256;                // k-pairs (bf16x2 along K)
constexpr int kAStrideU = 260;          // smA row stride (u32)
constexpr int kWStrideU = 36;           // smW col stride (u32)
constexpr int kTileK2 = 32;             // k-pairs per W tile
constexpr int kNIt = 8;
constexpr int kWTileU = kColsTot * kWStrideU;   // 12096
// smem layout (u32 units)
constexpr int kOffA  = 0;                        // 16*260 = 4160
constexpr int kOffW  = 4160;                     // 3 tiles -> 40448
// scan double-buffers live in [0, 10240) after GEMM is done
constexpr int kOffE0 = 41984;
constexpr int kOffE1 = kOffE0 + 256;
constexpr int kOffEs = kOffE1 + 256;
constexpr int kOffEa = kOffEs + 256;
constexpr int kOffY  = kOffEa + 256;             // y vectors 16x16
constexpr int kSmemU = kOffY + 256;              // 43264
constexpr int kSmemBytes = kSmemU * 4;           // 173056
constexpr int kMStrideRow = 20;
constexpr int kMStrideMat = 320;
constexpr int kNBatch = 8;              // 8 batches x 16 windows
}
#define EXP_NEG_PEN 0.60653065971263342f
#define LN2 0.69314718055994530942

// Cross-kernel / cross-block scratch.
__device__ u32    g_WbT[kColsTot * kK2];   // W transposed, bf16x2 k-paired
__device__ float  g_M[kNBlks * 256];
__device__ float  g_chk[(kNBlks + 1) * kB];
__device__ int    g_Eb[kNBlks + 1];
__device__ float  g_es0_fin[kB];
__device__ double g_tot;
__device__ unsigned g_rcnt;
__device__ unsigned g_wflag[kNBlks];   // per-window M ready (consumer resets)
__device__ unsigned g_scan_done;       // all checkpoints ready (finalizer resets)
__device__ unsigned g_fin_flag;        // es0_fin ready (blk127 resets)

// ---------------------------------------------------------------------------
// helpers
// ---------------------------------------------------------------------------
__device__ __forceinline__ void cp_async16(void* sdst, const void* gsrc) {
    unsigned a = (unsigned)__cvta_generic_to_shared(sdst);
    asm volatile("cp.async.cg.shared.global [%0], [%1], 16;" :: "r"(a), "l"(gsrc));
}
#define CP_COMMIT() asm volatile("cp.async.commit_group;")
#define CP_WAIT1()  asm volatile("cp.async.wait_group 1;")
#define CP_WAIT0()  asm volatile("cp.async.wait_group 0;")

__device__ __forceinline__ unsigned ld_acq(const unsigned* p) {
    unsigned v;
    asm volatile("ld.acquire.gpu.global.u32 %0, [%1];" : "=r"(v) : "l"(p) : "memory");
    return v;
}
__device__ __forceinline__ void st_rel(unsigned* p, unsigned v) {
    asm volatile("st.release.gpu.global.u32 [%0], %1;" :: "l"(p), "r"(v) : "memory");
}

__device__ __forceinline__ u32 pack_bf16(float lo, float hi) {
    unsigned short l = __bfloat16_as_ushort(__float2bfloat16_rn(lo));
    unsigned short h = __bfloat16_as_ushort(__float2bfloat16_rn(hi));
    return ((u32)h << 16) | (u32)l;
}
__device__ __forceinline__ void mma_bf16(float c[4], u32 a0, u32 a1, u32 a2,
                                         u32 a3, u32 b0, u32 b1) {
    asm("mma.sync.aligned.m16n8k16.row.col.f32.bf16.bf16.f32 "
        "{%0,%1,%2,%3},{%4,%5,%6,%7},{%8,%9},{%0,%1,%2,%3};"
        : "+f"(c[0]), "+f"(c[1]), "+f"(c[2]), "+f"(c[3])
        : "r"(a0), "r"(a1), "r"(a2), "r"(a3), "r"(b0), "r"(b1));
}
__device__ __forceinline__ void load16s(float d[16], const float* p) {
    const float4* p4 = (const float4*)p;
    float4 a = p4[0], b = p4[1], c = p4[2], e = p4[3];
    d[0]=a.x; d[1]=a.y; d[2]=a.z; d[3]=a.w;
    d[4]=b.x; d[5]=b.y; d[6]=b.z; d[7]=b.w;
    d[8]=c.x; d[9]=c.y; d[10]=c.z; d[11]=c.w;
    d[12]=e.x; d[13]=e.y; d[14]=e.z; d[15]=e.w;
}
__device__ __forceinline__ void load16g(float d[16], const float* p) {
    float4 a = __ldcg((const float4*)p);
    float4 b = __ldcg((const float4*)p + 1);
    float4 c = __ldcg((const float4*)p + 2);
    float4 e = __ldcg((const float4*)p + 3);
    d[0]=a.x; d[1]=a.y; d[2]=a.z; d[3]=a.w;
    d[4]=b.x; d[5]=b.y; d[6]=b.z; d[7]=b.w;
    d[8]=c.x; d[9]=c.y; d[10]=c.z; d[11]=c.w;
    d[12]=e.x; d[13]=e.y; d[14]=e.z; d[15]=e.w;
}
__device__ __forceinline__ float tree16(const float v[16]) {
    float a0=v[0]+v[1], a1=v[2]+v[3], a2=v[4]+v[5], a3=v[6]+v[7];
    float a4=v[8]+v[9], a5=v[10]+v[11], a6=v[12]+v[13], a7=v[14]+v[15];
    float b0=a0+a1, b1=a2+a3, b2=a4+a5, b3=a6+a7;
    return (b0+b1)+(b2+b3);
}

// ---------------------------------------------------------------------------
// K0: convert W -> transposed bf16 pairs
// ---------------------------------------------------------------------------
__global__ __launch_bounds__(256) void convert_w_kernel(
    const float* __restrict__ Wa,
    const float* __restrict__ Wsp,
    const float* __restrict__ Wst) {
    int idx = blockIdx.x * 256 + threadIdx.x;
    if (idx >= kColsTot * kK2) return;
    int k2 = idx / kColsTot;
    int col = idx - k2 * kColsTot;
    const float* base; int stride, off;
    if (col < 288)      { base = Wa;  stride = 288; off = col; }
    else if (col < 320) { base = Wsp; stride = 32;  off = col - 288; }
    else                { base = Wst; stride = 16;  off = col - 320; }
    float x0 = base[(2 * k2    ) * stride + off];
    float x1 = base[(2 * k2 + 1) * stride + off];
    g_WbT[col * kK2 + k2] = pack_bf16(x0, x1);
}

// ---------------------------------------------------------------------------
// K1: fused — A-pack, GEMM, softmax, compose(+y), OVERLAPPED scan, y-dot
// ---------------------------------------------------------------------------
__global__ __launch_bounds__(kThreads) void fused_kernel(
    const float* __restrict__ s_i,
    const void* __restrict__ actions_raw,
    float* __restrict__ out) {
    extern __shared__ __align__(16) u32 smem[];
    u32* smA = smem + kOffA;
    u32* smW = smem + kOffW;
    float* smL = (float*)(smem + kOffW);     // logits alias W buf0 after GEMM
    float* sE0 = (float*)(smem + kOffE0);
    float* sE1 = (float*)(smem + kOffE1);
    float* sEs = (float*)(smem + kOffEs);
    float* sEa = (float*)(smem + kOffEa);
    float* sY  = (float*)(smem + kOffY);
    __shared__ int s_is64;

    const int tid  = threadIdx.x;
    const int blk  = blockIdx.x;
    const int row0 = blk * kRowsPerBlk;

    if (tid == 0) {
        const unsigned* w = (const unsigned*)actions_raw;
        unsigned acc = 0;
#pragma unroll
        for (int j = 1; j < 64; j += 2) acc |= w[j];
        s_is64 = (acc == 0u) ? 1 : 0;
    }

    // ---- Phase 1a: W prestage (tiles p0, p0+1) + in-register A-pack ----
    const int p0 = blk & (kNIt - 1);
    {
        int tk2 = p0 * kTileK2;
#pragma unroll
        for (int h = 0; h < 4; h++) {
            int q = tid + h * kThreads;
            int col = q >> 3, ch = q & 7;
            cp_async16(smW + col * kWStrideU + ch * 4,
                       g_WbT + col * kK2 + tk2 + ch * 4);
        }
        CP_COMMIT();
        int tk2b = (((p0 + 1) & (kNIt - 1)) * kTileK2);
#pragma unroll
        for (int h = 0; h < 4; h++) {
            int q = tid + h * kThreads;
            int col = q >> 3, ch = q & 7;
            cp_async16(smW + kWTileU + col * kWStrideU + ch * 4,
                       g_WbT + col * kK2 + tk2b + ch * 4);
        }
        CP_COMMIT();
    }
#pragma unroll
    for (int h = 0; h < 2; h++) {
        int q = tid + h * kThreads;
        if (q < 1024) {
            int r  = q >> 6;
            int ch = q & 63;
            int gr = row0 + r;
            float4 f0 = make_float4(0.f, 0.f, 0.f, 0.f);
            float4 f1 = f0;
            if (gr <= kT) {
                const float4* src = (const float4*)(s_i + gr * kS + ch * 8);
                f0 = src[0];
                f1 = src[1];
            }
            uint4 pk;
            pk.x = pack_bf16(f0.x, f0.y);
            pk.y = pack_bf16(f0.z, f0.w);
            pk.z = pack_bf16(f1.x, f1.y);
            pk.w = pack_bf16(f1.z, f1.w);
            *(uint4*)(smA + r * kAStrideU + ch * 4) = pk;
        }
    }

    // ---- Phase 1b: bf16 tensor-core GEMM (m16n8k16) ----
    const int lane = tid & 31;
    const int wid  = tid >> 5;
    const int g    = lane >> 2;
    const int t    = lane & 3;
    const int cb0  = wid * 16;
    const int cb1  = cb0 + 8;

    float c0[4] = {0.f, 0.f, 0.f, 0.f};
    float c1[4] = {0.f, 0.f, 0.f, 0.f};

    for (int i = 0; i < kNIt; i++) {
        if (i == kNIt - 1) { CP_WAIT0(); } else { CP_WAIT1(); }
        __syncthreads();
        if (i + 2 < kNIt) {
            u32* d = smW + ((i + 2) % 3) * kWTileU;
            int tk2 = (((p0 + i + 2) & (kNIt - 1)) * kTileK2);
#pragma unroll
            for (int h = 0; h < 4; h++) {
                int q = tid + h * kThreads;
                int col = q >> 3, ch = q & 7;
                cp_async16(d + col * kWStrideU + ch * 4,
                           g_WbT + col * kK2 + tk2 + ch * 4);
            }
            CP_COMMIT();
        }
        const int phys = (p0 + i) & (kNIt - 1);
        const u32* wt = smW + (i % 3) * kWTileU;
        const int kb2 = phys * kTileK2;
#pragma unroll
        for (int kk = 0; kk < 4; kk++) {
            const int o  = kb2 + kk * 8;
            const int ot = kk * 8;
            u32 a0 = smA[(g    ) * kAStrideU + o + t    ];
            u32 a1 = smA[(g + 8) * kAStrideU + o + t    ];
            u32 a2 = smA[(g    ) * kAStrideU + o + t + 4];
            u32 a3 = smA[(g + 8) * kAStrideU + o + t + 4];
            u32 b00 = wt[(cb0 + g) * kWStrideU + ot + t    ];
            u32 b01 = wt[(cb0 + g) * kWStrideU + ot + t + 4];
            u32 b10 = wt[(cb1 + g) * kWStrideU + ot + t    ];
            u32 b11 = wt[(cb1 + g) * kWStrideU + ot + t + 4];
            mma_bf16(c0, a0, a1, a2, a3, b00, b01);
            mma_bf16(c1, a0, a1, a2, a3, b10, b11);
        }
    }
    __syncthreads();

    // ---- Phase 1c: epilogue — scatter C fragments to smL[r*336 + c] ----
    {
        int col0 = cb0 + 2 * t;
        smL[(g    ) * kColsTot + col0    ] = c0[0];
        smL[(g    ) * kColsTot + col0 + 1] = c0[1];
        smL[(g + 8) * kColsTot + col0    ] = c0[2];
        smL[(g + 8) * kColsTot + col0 + 1] = c0[3];
        int col1 = cb1 + 2 * t;
        smL[(g    ) * kColsTot + col1    ] = c1[0];
        smL[(g    ) * kColsTot + col1 + 1] = c1[1];
        smL[(g + 8) * kColsTot + col1    ] = c1[2];
        smL[(g + 8) * kColsTot + col1 + 1] = c1[3];
    }
    __syncthreads();

    // ---- Phase 1d: softmaxes ----
    if (tid < 256) {
        const int r = tid >> 4;
        const int b = tid & 15;
        const int i = row0 + r;
        const bool valid = (i <= kT);
        const int is64 = s_is64;

        if (valid) {
            if (i < kT) {
                int a;
                if (is64) a = (int)((const long long*)actions_raw)[i];
                else      a = ((const int*)actions_raw)[i];
                const float* L = &smL[r * kColsTot + b * kA];
                float m = L[0];
#pragma unroll
                for (int j = 1; j < kA; j++) m = fmaxf(m, L[j]);
                float s = 0.0f;
#pragma unroll
                for (int j = 0; j < kA; j++) s += __expf(L[j] - m);
                sEa[r * kB + b] = __expf(L[a] - m) / s;
            }
            float x0 = smL[r * kColsTot + 288 + 2 * b];
            float x1 = smL[r * kColsTot + 288 + 2 * b + 1];
            float m = fmaxf(x0, x1);
            float e0 = __expf(x0 - m), e1 = __expf(x1 - m);
            float inv = 1.0f / (e0 + e1);
            float es0 = e0 * inv;
            sE0[r * kB + b] = es0;
            sE1[r * kB + b] = e1 * inv;
            if (i == kT) g_es0_fin[b] = es0;
        }
        {
            float x = smL[r * kColsTot + 320 + b];
            float m = x;
            m = fmaxf(m, __shfl_xor_sync(0xFFFFFFFFu, m, 1));
            m = fmaxf(m, __shfl_xor_sync(0xFFFFFFFFu, m, 2));
            m = fmaxf(m, __shfl_xor_sync(0xFFFFFFFFu, m, 4));
            m = fmaxf(m, __shfl_xor_sync(0xFFFFFFFFu, m, 8));
            float e = __expf(x - m);
            float s = e;
            s += __shfl_xor_sync(0xFFFFFFFFu, s, 1);
            s += __shfl_xor_sync(0xFFFFFFFFu, s, 2);
            s += __shfl_xor_sync(0xFFFFFFFFu, s, 4);
            s += __shfl_xor_sync(0xFFFFFFFFu, s, 8);
            if (valid) sEs[r * kB + b] = e / s;
        }
    }
    __syncthreads();

    // block 128: es0_fin is now globally visible (post-sync) -> release flag
    if (blk == kNBlks && tid == 0) st_rel(&g_fin_flag, 1u);

    // ---- Phase 2: compose (+ y into smem); release per-window flag ----
    if (blk < kNBlks && tid < 32) {
        const int k = tid & 15;
        float P16[16];
#pragma unroll
        for (int j = 0; j < 16; j++) P16[j] = (j == k) ? 1.0f : 0.0f;
        for (int s = 0; s < kBlkSteps; s++) {
            if (!(blk == 0 && s == 0)) {
                float s0[16], s1[16], vv[16];
                load16s(s0, &sE0[s * kB]);
                load16s(s1, &sE1[s * kB]);
                load16s(vv, &sEs[s * kB]);
                float m[16];
#pragma unroll
                for (int j = 0; j < 16; j++) m[j] = s1[j] * P16[j];
                float w = tree16(m);
#pragma unroll
                for (int j = 0; j < 16; j++)
                    P16[j] = fmaf(s0[j], P16[j], (vv[j] * EXP_NEG_PEN) * w);
            }
            float ea[16];
            load16s(ea, &sEa[s * kB]);
            float m2[16];
#pragma unroll
            for (int j = 0; j < 16; j++) m2[j] = ea[j] * P16[j];
            float y = tree16(m2);
            if (tid < 16) sY[s * kB + k] = y;
        }
        if (tid < 16) {
#pragma unroll
            for (int j = 0; j < 16; j++)
                g_M[blk * 256 + j * 16 + k] = P16[j];
        }
        __syncwarp();
        if (tid == 0) st_rel(&g_wflag[blk], 1u);
    }

    // ---- Phase 3: OVERLAPPED serial scan (block 0) ----
    // Warps 1..20 = loaders: stream M windows (as their flags land) into a
    // double-buffered smem region while warp 0 scans the previous batch.
    if (blk == 0) {
        __syncthreads();   // compose done; smem [0,40960) free for buffers
        float* smM0 = (float*)smem;
        float* smM1 = (float*)smem + 16 * kMStrideMat;   // +5120 floats

        float Q[16];
        int E = 0;
        const int r = tid & 15;
        if (tid < 32) {
            load16s(Q, &sEs[0]);     // row 0 start softmax (block 0 owns it)
            if (tid < 16) g_chk[tid] = Q[tid];
            if (tid == 0) g_Eb[0] = 0;
        }

        // preload batch 0
        if (tid >= 32) {
            int lt = tid - 32;
#pragma unroll
            for (int h = 0; h < 2; h++) {
                int q = lt + h * 640;
                if (q < 1024) {
                    int jj = q >> 6;
                    while (ld_acq(&g_wflag[jj]) == 0u) __nanosleep(128);
                    int rem = q & 63, row = rem >> 2, ch = rem & 3;
                    cp_async16(smM0 + jj * kMStrideMat + row * kMStrideRow + ch * 4,
                               (const float*)g_M + jj * 256 + rem * 4);
                }
            }
            CP_COMMIT();
            CP_WAIT0();
        }
        __syncthreads();

        for (int b = 0; b < kNBatch; b++) {
            if (tid >= 32) {
                if (b + 1 < kNBatch) {
                    float* dst = ((b + 1) & 1) ? smM1 : smM0;
                    int lt = tid - 32;
#pragma unroll
                    for (int h = 0; h < 2; h++) {
                        int q = lt + h * 640;
                        if (q < 1024) {
                            int jj = q >> 6;
                            int j  = (b + 1) * 16 + jj;
                            while (ld_acq(&g_wflag[j]) == 0u) __nanosleep(128);
                            int rem = q & 63, row = rem >> 2, ch = rem & 3;
                            cp_async16(dst + jj * kMStrideMat + row * kMStrideRow + ch * 4,
                                       (const float*)g_M + j * 256 + rem * 4);
                        }
                    }
                    CP_COMMIT();
                    CP_WAIT0();
                }
            } else {
                float* buf = (b & 1) ? smM1 : smM0;
                float4 a0, a1, a2, a3;
                {
                    const float* Mr = buf + r * kMStrideRow;
                    a0 = *(const float4*)(Mr + 0);
                    a1 = *(const float4*)(Mr + 4);
                    a2 = *(const float4*)(Mr + 8);
                    a3 = *(const float4*)(Mr + 12);
                }
                for (int jj = 0; jj < 16; jj++) {
                    float4 b0, b1, b2, b3;
                    if (jj + 1 < 16) {
                        const float* Mn = buf + (jj + 1) * kMStrideMat + r * kMStrideRow;
                        b0 = *(const float4*)(Mn + 0);
                        b1 = *(const float4*)(Mn + 4);
                        b2 = *(const float4*)(Mn + 8);
                        b3 = *(const float4*)(Mn + 12);
                    }
                    const int j = b * 16 + jj;
                    float mm[16] = {a0.x, a0.y, a0.z, a0.w, a1.x, a1.y, a1.z, a1.w,
                                    a2.x, a2.y, a2.z, a2.w, a3.x, a3.y, a3.z, a3.w};
                    float pr[16];
#pragma unroll
                    for (int kk = 0; kk < 16; kk++) pr[kk] = mm[kk] * Q[kk];
                    float outr = tree16(pr);

                    float Qn[16];
#pragma unroll
                    for (int kk = 0; kk < 16; kk++)
                        Qn[kk] = __shfl_sync(0xFFFFFFFFu, outr, kk);

                    if ((j & 3) == 3) {
                        float ss = tree16(Qn);
                        int e = ((__float_as_int(ss) >> 23) & 0xFF) - 127;
                        float sc = __int_as_float((127 - e) << 23);
#pragma unroll
                        for (int kk = 0; kk < 16; kk++) Q[kk] = Qn[kk] * sc;
                        E += e;
                    } else {
#pragma unroll
                        for (int kk = 0; kk < 16; kk++) Q[kk] = Qn[kk];
                    }

                    if (tid < 16) g_chk[(j + 1) * kB + tid] = Q[tid];
                    if (tid == 0) g_Eb[j + 1] = E;
                    a0 = b0; a1 = b1; a2 = b2; a3 = b3;
                }
            }
            __syncthreads();
        }
        if (tid == 0) st_rel(&g_scan_done, 1u);
        if (tid < kNBlks) g_wflag[tid] = 0u;   // consumer reset for replay
    }

    // ---- Phase 4: y-dot tot (16 threads/block) + atomic reduction ----
    if (blk < kNBlks && tid < 32) {
        if (blk != 0) {
            if (tid == 0) {
                while (ld_acq(&g_scan_done) == 0u) __nanosleep(128);
            }
            __syncwarp();
        }
        if (blk == kNBlks - 1) {
            if (tid == 0) {
                while (ld_acq(&g_fin_flag) == 0u) __nanosleep(64);
                g_fin_flag = 0u;   // consumer reset
            }
            __syncwarp();
        }
        if (tid < 16) {
            float c[16];
            load16g(c, &g_chk[blk * kB]);
            const int E = __ldcg(&g_Eb[blk]);
            float y[16];
            load16s(y, &sY[tid * kB]);
            float pr[16];
#pragma unroll
            for (int kk = 0; kk < 16; kk++) pr[kk] = y[kk] * c[kk];
            float u = tree16(pr);
            double acc = (double)__logf(u);

#pragma unroll
            for (int o = 8; o > 0; o >>= 1)
                acc += __shfl_down_sync(0x0000FFFFu, acc, o, 16);

            if (tid == 0) {
                acc += (double)(kBlkSteps * E) * LN2;
                if (blk == kNBlks - 1) {
                    float f[16], cf[16];
                    load16g(f, g_es0_fin);
                    load16g(cf, &g_chk[kNBlks * kB]);
                    float p2[16];
#pragma unroll
                    for (int kk = 0; kk < 16; kk++) p2[kk] = f[kk] * cf[kk];
                    float uf = tree16(p2);
                    acc += (double)__logf(uf) + (double)__ldcg(&g_Eb[kNBlks]) * LN2;
                }
                atomicAdd(&g_tot, acc);
                __threadfence();
                unsigned old = atomicAdd(&g_rcnt, 1u);
                if (old == (unsigned)(kNBlks - 1)) {
                    __threadfence();
                    double v = atomicAdd(&g_tot, 0.0);
                    out[0] = (float)v;
                    g_rcnt = 0u;
                    g_tot = 0.0;
                    g_scan_done = 0u;   // finalizer reset (all consumers passed)
                    __threadfence();
                }
            }
        }
    }
}

// ---------------------------------------------------------------------------
// Launch
// ---------------------------------------------------------------------------
extern "C" void kernel_launch(void* const* d_in, const int* in_sizes, int n_in,
                              void* d_out, int out_size) {
    const float* s_i = (const float*)d_in[0];
    const float* Wa  = (const float*)d_in[1];
    const float* Wsp = (const float*)d_in[2];
    const float* Wst = (const float*)d_in[3];
    const void*  act = d_in[4];

    cudaFuncSetAttribute(fused_kernel,
                         cudaFuncAttributeMaxDynamicSharedMemorySize,
                         kSmemBytes);

    convert_w_kernel<<<(kColsTot * kK2 + 255) / 256, 256>>>(Wa, Wsp, Wst);
    fused_kernel<<<kGrid, kThreads, kSmemBytes>>>(s_i, act, (float*)d_out);
}